// round 7
// baseline (speedup 1.0000x reference)
#include <cuda_runtime.h>

// Batched DLT: 262144 independent 8x8 systems, h = pinv(A)@b == solve(A,b).
// R7: issue/latency-bound tuning on top of the R6 structure:
//  - occupancy: launch_bounds(256,5) -> <=51 regs, 5 CTAs/SM (was 4)
//  - b-dots (w.vp, w.up) demoted df64 -> plain fp32 FMA (z err ~1e-6, gate 1e-3)
//  - df64 retained only for det2 + Cramer numerators (2^43-scale cancellation)
//  - exact-integer skeleton and exact fp32 trunc-emulation unchanged

struct df { float h, l; };

__device__ __forceinline__ float2 two_sum(float a, float b) {
    float s = a + b; float bb = s - a;
    float e = (a - (s - bb)) + (b - bb);
    return make_float2(s, e);
}
__device__ __forceinline__ df qts(float a, float b) {   // |a| >= |b|
    float s = a + b; float e = b - (s - a);
    return df{s, e};
}
__device__ __forceinline__ df df_add(df x, df y) {
    float2 s = two_sum(x.h, y.h);
    s.y += x.l + y.l;
    return qts(s.x, s.y);
}
__device__ __forceinline__ df df_sub(df x, df y) {
    return df_add(x, df{-y.h, -y.l});
}
__device__ __forceinline__ df df_mul(df x, df y) {
    float p = x.h * y.h;
    float e = fmaf(x.h, y.h, -p);
    e += fmaf(x.h, y.l, x.l * y.h);
    return qts(p, e);
}
__device__ __forceinline__ df df_smul(df x, float s) {   // df * exact scalar
    float p = x.h * s;
    float e = fmaf(x.h, s, -p);
    e = fmaf(x.l, s, e);
    return qts(p, e);
}
__device__ __forceinline__ df df_from_ll(long long v) {  // exact for |v|<2^48
    float h = (float)v;
    float l = (float)(v - (long long)h);
    return df{h, l};
}
__device__ __forceinline__ df df_recip(df x) {
    float r0 = __frcp_rn(x.h);
    float e = fmaf(x.h, r0, -1.0f);
    e = fmaf(x.l, r0, e);
    return qts(r0, -r0 * e);
}

// Exact trunc(a*b) matching fp64 semantics. V = p + e (exact product);
// frac = p - trunc(p) is a multiple of ulp(p), |e| <= ulp(p)/2, so only the
// frac == 0 case can flip the integer part.
__device__ __forceinline__ int trunc_prod(float a, float b) {
    float p = a * b;
    float e = fmaf(a, b, -p);
    int it = (int)p;
    float t = (float)it;
    float d = (p - t) + e;
    if (d < 0.0f && it > 0) it -= 1;
    if (d > 0.0f && it < 0) it += 1;
    return it;
}

__global__ __launch_bounds__(256, 5)
void dlt_kernel(const float* __restrict__ x, const float* __restrict__ xp,
                float* __restrict__ out, int B)
{
    int i = blockIdx.x * blockDim.x + threadIdx.x;
    if (i >= B) return;

    float4 a0 = reinterpret_cast<const float4*>(x)[2*i + 0];
    float4 a1 = reinterpret_cast<const float4*>(x)[2*i + 1];
    float4 p0 = reinterpret_cast<const float4*>(xp)[2*i + 0];
    float4 p1 = reinterpret_cast<const float4*>(xp)[2*i + 1];

    float u0 = a0.x, v0 = a0.y, u1 = a0.z, v1 = a0.w;
    float u2 = a1.x, v2 = a1.y, u3 = a1.z, v3 = a1.w;
    float up0 = p0.x, vp0 = p0.y, up1 = p0.z, vp1 = p0.w;
    float up2 = p1.x, vp2 = p1.y, up3 = p1.z, vp3 = p1.w;

    // trunc of raw coordinates: exact F2I.
    int tu0 = (int)u0, tv0 = (int)v0, tu1 = (int)u1, tv1 = (int)v1;
    int tu2 = (int)u2, tv2 = (int)v2, tu3 = (int)u3, tv3 = (int)v3;

    // trunc(vp*u) etc. — exact, pure fp32+int.
    int cu0 = trunc_prod(vp0, u0), cu1 = trunc_prod(vp1, u1);
    int cu2 = trunc_prod(vp2, u2), cu3 = trunc_prod(vp3, u3);
    int cv0 = trunc_prod(vp0, v0), cv1 = trunc_prod(vp1, v1);
    int cv2 = trunc_prod(vp2, v2), cv3 = trunc_prod(vp3, v3);
    int du0 = trunc_prod(up0, u0), du1 = trunc_prod(up1, u1);
    int du2 = trunc_prod(up2, u2), du3 = trunc_prod(up3, u3);
    int dv0 = trunc_prod(up0, v0), dv1 = trunc_prod(up1, v1);
    int dv2 = trunc_prod(up2, v2), dv3 = trunc_prod(up3, v3);

    // Pairwise dets + left null vector w of M — exact int32.
    int D01 = tu0*tv1 - tu1*tv0;
    int D02 = tu0*tv2 - tu2*tv0;
    int D03 = tu0*tv3 - tu3*tv0;
    int D12 = tu1*tv2 - tu2*tv1;
    int D13 = tu1*tv3 - tu3*tv1;
    int D23 = tu2*tv3 - tu3*tv2;
    int w0 = D12 + D23 - D13;
    int w1 = D03 - D02 - D23;
    int w2 = D01 + D13 - D03;
    int w3 = D02 - D01 - D12;

    // 2x2 normal-matrix entries — exact int64 (|.| < 2^43).
    long long a11 = (long long)w0*cu0 + (long long)w1*cu1 + (long long)w2*cu2 + (long long)w3*cu3;
    long long a12 = (long long)w0*cv0 + (long long)w1*cv1 + (long long)w2*cv2 + (long long)w3*cv3;
    long long a21 = (long long)w0*du0 + (long long)w1*du1 + (long long)w2*du2 + (long long)w3*du3;
    long long a22 = (long long)w0*dv0 + (long long)w1*dv1 + (long long)w2*dv2 + (long long)w3*dv3;
    df A11 = df_from_ll(a11), A12 = df_from_ll(a12);
    df A21 = df_from_ll(a21), A22 = df_from_ll(a22);

    // b-dots in plain fp32 (rel err ~1e-7 on b; z err ~1e-6 after solve).
    float w0f = (float)w0, w1f = (float)w1, w2f = (float)w2, w3f = (float)w3;
    float b1 = -fmaf(w0f, vp0, fmaf(w1f, vp1, fmaf(w2f, vp2, w3f * vp3)));
    float b2 = -fmaf(w0f, up0, fmaf(w1f, up1, fmaf(w2f, up2, w3f * up3)));

    // z = (h7,h8) via Cramer (df for the 2^43-scale cancellations).
    df det2 = df_sub(df_mul(A11, A22), df_mul(A12, A21));
    df inv2 = df_recip(det2);
    df n1 = df_sub(df_smul(A22, b1), df_smul(A12, b2));
    df n2 = df_sub(df_smul(A11, b2), df_smul(A21, b1));
    df z1d = df_mul(n1, inv2);
    df z2d = df_mul(n2, inv2);
    float z1 = z1d.h + z1d.l;
    float z2 = z2d.h + z2d.l;

    // RHS of the two 3x3 solves — plain fp32.
    float gx0 = fmaf((float)du0, z1, fmaf((float)dv0, z2, up0));
    float gx1 = fmaf((float)du1, z1, fmaf((float)dv1, z2, up1));
    float gx2 = fmaf((float)du2, z1, fmaf((float)dv2, z2, up2));
    float gx3 = fmaf((float)du3, z1, fmaf((float)dv3, z2, up3));
    float gy0 = fmaf((float)cu0, z1, fmaf((float)cv0, z2, vp0));
    float gy1 = fmaf((float)cu1, z1, fmaf((float)cv1, z2, vp1));
    float gy2 = fmaf((float)cu2, z1, fmaf((float)cv2, z2, vp2));
    float gy3 = fmaf((float)cu3, z1, fmaf((float)cv3, z2, vp3));

    // Pivot: drop row argmax|w|.
    int aw0 = abs(w0), aw1 = abs(w1), aw2 = abs(w2), aw3 = abs(w3);
    int k = 0, awm = aw0;
    if (aw1 > awm) { k = 1; awm = aw1; }
    if (aw2 > awm) { k = 2; awm = aw2; }
    if (aw3 > awm) { k = 3; awm = aw3; }
    bool c0 = (k == 0), c1 = (k <= 1), c2 = (k <= 2);

    int A1i = c0 ? tu1 : tu0,  B1i = c0 ? tv1 : tv0;
    int A2i = c1 ? tu2 : tu1,  B2i = c1 ? tv2 : tv1;
    int A3i = c2 ? tu3 : tu2,  B3i = c2 ? tv3 : tv2;
    float G1x = c0 ? gx1 : gx0, G1y = c0 ? gy1 : gy0;
    float G2x = c1 ? gx2 : gx1, G2y = c1 ? gy2 : gy1;
    float G3x = c2 ? gx3 : gx2, G3y = c2 ? gy3 : gy2;

    // 3x3 adjugate — exact int32, fp32 solve.
    int E12 = A1i*B2i - A2i*B1i;
    int E23 = A2i*B3i - A3i*B2i;
    int E31 = A3i*B1i - A1i*B3i;
    int det3 = E12 + E23 + E31;
    float inv3 = __frcp_rn((float)det3);

    float r11 = (float)(B2i - B3i), r12 = (float)(B3i - B1i), r13 = (float)(B1i - B2i);
    float r21 = (float)(A3i - A2i), r22 = (float)(A1i - A3i), r23 = (float)(A2i - A1i);
    float e12 = (float)E12, e23 = (float)E23, e31 = (float)E31;

    float x1c = fmaf(r11, G1x, fmaf(r12, G2x, r13 * G3x)) * inv3;
    float x2c = fmaf(r21, G1x, fmaf(r22, G2x, r23 * G3x)) * inv3;
    float x3c = fmaf(e23, G1x, fmaf(e31, G2x, e12 * G3x)) * inv3;
    float y1c = fmaf(r11, G1y, fmaf(r12, G2y, r13 * G3y)) * inv3;
    float y2c = fmaf(r21, G1y, fmaf(r22, G2y, r23 * G3y)) * inv3;
    float y3c = fmaf(e23, G1y, fmaf(e31, G2y, e12 * G3y)) * inv3;

    float* o = out + (size_t)i * 9;
    o[0] = x1c; o[1] = x2c; o[2] = x3c;
    o[3] = y1c; o[4] = y2c; o[5] = y3c;
    o[6] = z1;  o[7] = z2;  o[8] = 1.0f;
}

extern "C" void kernel_launch(void* const* d_in, const int* in_sizes, int n_in,
                              void* d_out, int out_size)
{
    const float* x  = (const float*)d_in[0];
    const float* xp = (const float*)d_in[1];
    float* out = (float*)d_out;
    int B = in_sizes[0] / 8;
    int Bo = out_size / 9;
    if (Bo < B) B = Bo;
    dlt_kernel<<<(B + 255) / 256, 256>>>(x, xp, out, B);
}

// round 9
// speedup vs baseline: 1.1400x; 1.1400x over previous
#include <cuda_runtime.h>

// Batched DLT: 262144 independent 8x8 systems, h = pinv(A)@b == solve(A,b).
// R8: instruction-count diet (measured 880 instrs/thread at 50% issue, no
// pipe >23% -> count is the binding resource):
//  - EXACT trunc(a*b) in 2 instrs: (int)__fmul_rz(a,b). Proof: n=trunc(V) is
//    representable and |n|<=|V|, so RZ rounding cannot cross it:
//    |n| <= |rz(V)| <= |V| < |n|+1  =>  trunc(rz(V)) = trunc(V).
//  - df64 only for det2 / Cramer numerators (2^43-scale cancellation);
//    final z division collapses to fp32 (adds ~1e-7 rel, gate is 1e-3).
//  - launch_bounds(256,4): no spills (R7's forced 48 regs spilled to L1).
// Integer skeleton (dets, w, int64 normal-matrix dots, 3x3 cofactors) exact.

struct df { float h, l; };

__device__ __forceinline__ float2 two_sum(float a, float b) {
    float s = a + b; float bb = s - a;
    float e = (a - (s - bb)) + (b - bb);
    return make_float2(s, e);
}
__device__ __forceinline__ df qts(float a, float b) {   // |a| >= |b|
    float s = a + b; float e = b - (s - a);
    return df{s, e};
}
__device__ __forceinline__ df df_add(df x, df y) {
    float2 s = two_sum(x.h, y.h);
    s.y += x.l + y.l;
    return qts(s.x, s.y);
}
__device__ __forceinline__ df df_sub(df x, df y) {
    return df_add(x, df{-y.h, -y.l});
}
__device__ __forceinline__ df df_mul(df x, df y) {
    float p = x.h * y.h;
    float e = fmaf(x.h, y.h, -p);
    e += fmaf(x.h, y.l, x.l * y.h);
    return qts(p, e);
}
__device__ __forceinline__ df df_smul(df x, float s) {   // df * exact scalar
    float p = x.h * s;
    float e = fmaf(x.h, s, -p);
    e = fmaf(x.l, s, e);
    return qts(p, e);
}
__device__ __forceinline__ df df_from_ll(long long v) {  // exact for |v|<2^48
    float h = (float)v;
    float l = (float)(v - (long long)h);
    return df{h, l};
}

// Exact trunc(a*b) == fp64-trunc semantics in two instructions (see header).
__device__ __forceinline__ int trunc_prod(float a, float b) {
    return (int)__fmul_rz(a, b);
}

__global__ __launch_bounds__(256, 4)
void dlt_kernel(const float* __restrict__ x, const float* __restrict__ xp,
                float* __restrict__ out, int B)
{
    int i = blockIdx.x * blockDim.x + threadIdx.x;
    if (i >= B) return;

    float4 a0 = reinterpret_cast<const float4*>(x)[2*i + 0];
    float4 a1 = reinterpret_cast<const float4*>(x)[2*i + 1];
    float4 p0 = reinterpret_cast<const float4*>(xp)[2*i + 0];
    float4 p1 = reinterpret_cast<const float4*>(xp)[2*i + 1];

    float u0 = a0.x, v0 = a0.y, u1 = a0.z, v1 = a0.w;
    float u2 = a1.x, v2 = a1.y, u3 = a1.z, v3 = a1.w;
    float up0 = p0.x, vp0 = p0.y, up1 = p0.z, vp1 = p0.w;
    float up2 = p1.x, vp2 = p1.y, up3 = p1.z, vp3 = p1.w;

    // trunc of raw coordinates: exact F2I.
    int tu0 = (int)u0, tv0 = (int)v0, tu1 = (int)u1, tv1 = (int)v1;
    int tu2 = (int)u2, tv2 = (int)v2, tu3 = (int)u3, tv3 = (int)v3;

    // trunc(vp*u) etc. — exact via RZ multiply + F2I.
    int cu0 = trunc_prod(vp0, u0), cu1 = trunc_prod(vp1, u1);
    int cu2 = trunc_prod(vp2, u2), cu3 = trunc_prod(vp3, u3);
    int cv0 = trunc_prod(vp0, v0), cv1 = trunc_prod(vp1, v1);
    int cv2 = trunc_prod(vp2, v2), cv3 = trunc_prod(vp3, v3);
    int du0 = trunc_prod(up0, u0), du1 = trunc_prod(up1, u1);
    int du2 = trunc_prod(up2, u2), du3 = trunc_prod(up3, u3);
    int dv0 = trunc_prod(up0, v0), dv1 = trunc_prod(up1, v1);
    int dv2 = trunc_prod(up2, v2), dv3 = trunc_prod(up3, v3);

    // Pairwise dets + left null vector w of M — exact int32.
    int D01 = tu0*tv1 - tu1*tv0;
    int D02 = tu0*tv2 - tu2*tv0;
    int D03 = tu0*tv3 - tu3*tv0;
    int D12 = tu1*tv2 - tu2*tv1;
    int D13 = tu1*tv3 - tu3*tv1;
    int D23 = tu2*tv3 - tu3*tv2;
    int w0 = D12 + D23 - D13;
    int w1 = D03 - D02 - D23;
    int w2 = D01 + D13 - D03;
    int w3 = D02 - D01 - D12;

    // 2x2 normal-matrix entries — exact int64 (|.| < 2^43).
    long long a11 = (long long)w0*cu0 + (long long)w1*cu1 + (long long)w2*cu2 + (long long)w3*cu3;
    long long a12 = (long long)w0*cv0 + (long long)w1*cv1 + (long long)w2*cv2 + (long long)w3*cv3;
    long long a21 = (long long)w0*du0 + (long long)w1*du1 + (long long)w2*du2 + (long long)w3*du3;
    long long a22 = (long long)w0*dv0 + (long long)w1*dv1 + (long long)w2*dv2 + (long long)w3*dv3;
    df A11 = df_from_ll(a11), A12 = df_from_ll(a12);
    df A21 = df_from_ll(a21), A22 = df_from_ll(a22);

    // b-dots in plain fp32 (z rel err ~1e-6 after solve; gate 1e-3).
    float w0f = (float)w0, w1f = (float)w1, w2f = (float)w2, w3f = (float)w3;
    float b1 = -fmaf(w0f, vp0, fmaf(w1f, vp1, fmaf(w2f, vp2, w3f * vp3)));
    float b2 = -fmaf(w0f, up0, fmaf(w1f, up1, fmaf(w2f, up2, w3f * up3)));

    // z via Cramer: df only for the 2^43-scale cancelling sums, then fp32.
    df det2 = df_sub(df_mul(A11, A22), df_mul(A12, A21));
    df n1 = df_sub(df_smul(A22, b1), df_smul(A12, b2));
    df n2 = df_sub(df_smul(A11, b2), df_smul(A21, b1));
    float inv2 = __frcp_rn(det2.h + det2.l);
    float z1 = (n1.h + n1.l) * inv2;
    float z2 = (n2.h + n2.l) * inv2;

    // RHS of the two 3x3 solves — plain fp32.
    float gx0 = fmaf((float)du0, z1, fmaf((float)dv0, z2, up0));
    float gx1 = fmaf((float)du1, z1, fmaf((float)dv1, z2, up1));
    float gx2 = fmaf((float)du2, z1, fmaf((float)dv2, z2, up2));
    float gx3 = fmaf((float)du3, z1, fmaf((float)dv3, z2, up3));
    float gy0 = fmaf((float)cu0, z1, fmaf((float)cv0, z2, vp0));
    float gy1 = fmaf((float)cu1, z1, fmaf((float)cv1, z2, vp1));
    float gy2 = fmaf((float)cu2, z1, fmaf((float)cv2, z2, vp2));
    float gy3 = fmaf((float)cu3, z1, fmaf((float)cv3, z2, vp3));

    // Pivot: drop row argmax|w|.
    int aw0 = abs(w0), aw1 = abs(w1), aw2 = abs(w2), aw3 = abs(w3);
    int k = 0, awm = aw0;
    if (aw1 > awm) { k = 1; awm = aw1; }
    if (aw2 > awm) { k = 2; awm = aw2; }
    if (aw3 > awm) { k = 3; awm = aw3; }
    bool c0 = (k == 0), c1 = (k <= 1), c2 = (k <= 2);

    int A1i = c0 ? tu1 : tu0,  B1i = c0 ? tv1 : tv0;
    int A2i = c1 ? tu2 : tu1,  B2i = c1 ? tv2 : tv1;
    int A3i = c2 ? tu3 : tu2,  B3i = c2 ? tv3 : tv2;
    float G1x = c0 ? gx1 : gx0, G1y = c0 ? gy1 : gy0;
    float G2x = c1 ? gx2 : gx1, G2y = c1 ? gy2 : gy1;
    float G3x = c2 ? gx3 : gx2, G3y = c2 ? gy3 : gy2;

    // 3x3 adjugate — exact int32, fp32 solve.
    int E12 = A1i*B2i - A2i*B1i;
    int E23 = A2i*B3i - A3i*B2i;
    int E31 = A3i*B1i - A1i*B3i;
    int det3 = E12 + E23 + E31;
    float inv3 = __frcp_rn((float)det3);

    float r11 = (float)(B2i - B3i), r12 = (float)(B3i - B1i), r13 = (float)(B1i - B2i);
    float r21 = (float)(A3i - A2i), r22 = (float)(A1i - A3i), r23 = (float)(A2i - A1i);
    float e12 = (float)E12, e23 = (float)E23, e31 = (float)E31;

    float x1c = fmaf(r11, G1x, fmaf(r12, G2x, r13 * G3x)) * inv3;
    float x2c = fmaf(r21, G1x, fmaf(r22, G2x, r23 * G3x)) * inv3;
    float x3c = fmaf(e23, G1x, fmaf(e31, G2x, e12 * G3x)) * inv3;
    float y1c = fmaf(r11, G1y, fmaf(r12, G2y, r13 * G3y)) * inv3;
    float y2c = fmaf(r21, G1y, fmaf(r22, G2y, r23 * G3y)) * inv3;
    float y3c = fmaf(e23, G1y, fmaf(e31, G2y, e12 * G3y)) * inv3;

    float* o = out + (size_t)i * 9;
    o[0] = x1c; o[1] = x2c; o[2] = x3c;
    o[3] = y1c; o[4] = y2c; o[5] = y3c;
    o[6] = z1;  o[7] = z2;  o[8] = 1.0f;
}

extern "C" void kernel_launch(void* const* d_in, const int* in_sizes, int n_in,
                              void* d_out, int out_size)
{
    const float* x  = (const float*)d_in[0];
    const float* xp = (const float*)d_in[1];
    float* out = (float*)d_out;
    int B = in_sizes[0] / 8;
    int Bo = out_size / 9;
    if (Bo < B) B = Bo;
    dlt_kernel<<<(B + 255) / 256, 256>>>(x, xp, out, B);
}

// round 10
// speedup vs baseline: 1.1429x; 1.0025x over previous
#include <cuda_runtime.h>

// Batched DLT: 262144 independent 8x8 systems, h = pinv(A)@b == solve(A,b).
// R9: remove the df64 renormalization machinery (serial qts/two_sum chains)
// entirely. High-precision differences now use Kahan's compensated 2x2
// determinant on hi/lo-split int64 inputs:
//   d0 = (ab - ce) exactly via 2 FMAs + sub  (~1.5 ulp of true value)
//   + hi*lo cross-term corrections (4 FMAs)
// Everything else: exact int skeleton, exact 2-instr trunc ((int)__fmul_rz),
// fp32 FMA tails. 128-thread blocks for finer SM packing.

struct hl { float h, l; };

__device__ __forceinline__ hl split_ll(long long v) {   // exact for |v|<2^48
    float h = (float)v;
    float l = (float)(v - (long long)h);
    return hl{h, l};
}

// Kahan: returns a*b - c*e with ~1.5 ulp error (flat 4-op tree).
__device__ __forceinline__ float kdet(float a, float b, float c, float e) {
    float w  = c * e;
    float e1 = fmaf(c, e, -w);
    float f  = fmaf(a, b, -w);
    return f - e1;
}

__global__ __launch_bounds__(128)
void dlt_kernel(const float* __restrict__ x, const float* __restrict__ xp,
                float* __restrict__ out, int B)
{
    int i = blockIdx.x * blockDim.x + threadIdx.x;
    if (i >= B) return;

    float4 a0 = reinterpret_cast<const float4*>(x)[2*i + 0];
    float4 a1 = reinterpret_cast<const float4*>(x)[2*i + 1];
    float4 p0 = reinterpret_cast<const float4*>(xp)[2*i + 0];
    float4 p1 = reinterpret_cast<const float4*>(xp)[2*i + 1];

    float u0 = a0.x, v0 = a0.y, u1 = a0.z, v1 = a0.w;
    float u2 = a1.x, v2 = a1.y, u3 = a1.z, v3 = a1.w;
    float up0 = p0.x, vp0 = p0.y, up1 = p0.z, vp1 = p0.w;
    float up2 = p1.x, vp2 = p1.y, up3 = p1.z, vp3 = p1.w;

    // trunc of raw coordinates: exact F2I.
    int tu0 = (int)u0, tv0 = (int)v0, tu1 = (int)u1, tv1 = (int)v1;
    int tu2 = (int)u2, tv2 = (int)v2, tu3 = (int)u3, tv3 = (int)v3;

    // trunc(vp*u) etc.: exact — RZ multiply cannot cross the integer below |V|.
    int cu0 = (int)__fmul_rz(vp0, u0), cu1 = (int)__fmul_rz(vp1, u1);
    int cu2 = (int)__fmul_rz(vp2, u2), cu3 = (int)__fmul_rz(vp3, u3);
    int cv0 = (int)__fmul_rz(vp0, v0), cv1 = (int)__fmul_rz(vp1, v1);
    int cv2 = (int)__fmul_rz(vp2, v2), cv3 = (int)__fmul_rz(vp3, v3);
    int du0 = (int)__fmul_rz(up0, u0), du1 = (int)__fmul_rz(up1, u1);
    int du2 = (int)__fmul_rz(up2, u2), du3 = (int)__fmul_rz(up3, u3);
    int dv0 = (int)__fmul_rz(up0, v0), dv1 = (int)__fmul_rz(up1, v1);
    int dv2 = (int)__fmul_rz(up2, v2), dv3 = (int)__fmul_rz(up3, v3);

    // Pairwise dets + left null vector w of M — exact int32.
    int D01 = tu0*tv1 - tu1*tv0;
    int D02 = tu0*tv2 - tu2*tv0;
    int D03 = tu0*tv3 - tu3*tv0;
    int D12 = tu1*tv2 - tu2*tv1;
    int D13 = tu1*tv3 - tu3*tv1;
    int D23 = tu2*tv3 - tu3*tv2;
    int w0 = D12 + D23 - D13;
    int w1 = D03 - D02 - D23;
    int w2 = D01 + D13 - D03;
    int w3 = D02 - D01 - D12;

    // 2x2 normal-matrix entries — exact int64 (|.| < 2^43), hi/lo split.
    long long a11 = (long long)w0*cu0 + (long long)w1*cu1 + (long long)w2*cu2 + (long long)w3*cu3;
    long long a12 = (long long)w0*cv0 + (long long)w1*cv1 + (long long)w2*cv2 + (long long)w3*cv3;
    long long a21 = (long long)w0*du0 + (long long)w1*du1 + (long long)w2*du2 + (long long)w3*du3;
    long long a22 = (long long)w0*dv0 + (long long)w1*dv1 + (long long)w2*dv2 + (long long)w3*dv3;
    hl A11 = split_ll(a11), A12 = split_ll(a12);
    hl A21 = split_ll(a21), A22 = split_ll(a22);

    // b-dots in plain fp32.
    float w0f = (float)w0, w1f = (float)w1, w2f = (float)w2, w3f = (float)w3;
    float b1 = -fmaf(w0f, vp0, fmaf(w1f, vp1, fmaf(w2f, vp2, w3f * vp3)));
    float b2 = -fmaf(w0f, up0, fmaf(w1f, up1, fmaf(w2f, up2, w3f * up3)));

    // det2 = A11*A22 - A12*A21: Kahan hi-product diff + hi*lo corrections.
    float d0 = kdet(A11.h, A22.h, A12.h, A21.h);
    float dc = fmaf(A11.h, A22.l,
               fmaf(A11.l, A22.h,
              -fmaf(A12.h, A21.l, A12.l * A21.h)));
    float det2 = d0 + dc;

    // Cramer numerators (A entries hi/lo, b fp32).
    float n1 = kdet(A22.h, b1, A12.h, b2) + fmaf(A22.l, b1, -(A12.l * b2));
    float n2 = kdet(A11.h, b2, A21.h, b1) + fmaf(A11.l, b2, -(A21.l * b1));

    float inv2 = __frcp_rn(det2);
    float z1 = n1 * inv2;
    float z2 = n2 * inv2;

    // RHS of the two 3x3 solves — plain fp32.
    float gx0 = fmaf((float)du0, z1, fmaf((float)dv0, z2, up0));
    float gx1 = fmaf((float)du1, z1, fmaf((float)dv1, z2, up1));
    float gx2 = fmaf((float)du2, z1, fmaf((float)dv2, z2, up2));
    float gx3 = fmaf((float)du3, z1, fmaf((float)dv3, z2, up3));
    float gy0 = fmaf((float)cu0, z1, fmaf((float)cv0, z2, vp0));
    float gy1 = fmaf((float)cu1, z1, fmaf((float)cv1, z2, vp1));
    float gy2 = fmaf((float)cu2, z1, fmaf((float)cv2, z2, vp2));
    float gy3 = fmaf((float)cu3, z1, fmaf((float)cv3, z2, vp3));

    // Pivot: drop row argmax|w|.
    int aw0 = abs(w0), aw1 = abs(w1), aw2 = abs(w2), aw3 = abs(w3);
    int k = 0, awm = aw0;
    if (aw1 > awm) { k = 1; awm = aw1; }
    if (aw2 > awm) { k = 2; awm = aw2; }
    if (aw3 > awm) { k = 3; awm = aw3; }
    bool c0 = (k == 0), c1 = (k <= 1), c2 = (k <= 2);

    int A1i = c0 ? tu1 : tu0,  B1i = c0 ? tv1 : tv0;
    int A2i = c1 ? tu2 : tu1,  B2i = c1 ? tv2 : tv1;
    int A3i = c2 ? tu3 : tu2,  B3i = c2 ? tv3 : tv2;
    float G1x = c0 ? gx1 : gx0, G1y = c0 ? gy1 : gy0;
    float G2x = c1 ? gx2 : gx1, G2y = c1 ? gy2 : gy1;
    float G3x = c2 ? gx3 : gx2, G3y = c2 ? gy3 : gy2;

    // 3x3 adjugate — exact int32, fp32 solve.
    int E12 = A1i*B2i - A2i*B1i;
    int E23 = A2i*B3i - A3i*B2i;
    int E31 = A3i*B1i - A1i*B3i;
    int det3 = E12 + E23 + E31;
    float inv3 = __frcp_rn((float)det3);

    float r11 = (float)(B2i - B3i), r12 = (float)(B3i - B1i), r13 = (float)(B1i - B2i);
    float r21 = (float)(A3i - A2i), r22 = (float)(A1i - A3i), r23 = (float)(A2i - A1i);
    float e12 = (float)E12, e23 = (float)E23, e31 = (float)E31;

    float x1c = fmaf(r11, G1x, fmaf(r12, G2x, r13 * G3x)) * inv3;
    float x2c = fmaf(r21, G1x, fmaf(r22, G2x, r23 * G3x)) * inv3;
    float x3c = fmaf(e23, G1x, fmaf(e31, G2x, e12 * G3x)) * inv3;
    float y1c = fmaf(r11, G1y, fmaf(r12, G2y, r13 * G3y)) * inv3;
    float y2c = fmaf(r21, G1y, fmaf(r22, G2y, r23 * G3y)) * inv3;
    float y3c = fmaf(e23, G1y, fmaf(e31, G2y, e12 * G3y)) * inv3;

    float* o = out + (size_t)i * 9;
    o[0] = x1c; o[1] = x2c; o[2] = x3c;
    o[3] = y1c; o[4] = y2c; o[5] = y3c;
    o[6] = z1;  o[7] = z2;  o[8] = 1.0f;
}

extern "C" void kernel_launch(void* const* d_in, const int* in_sizes, int n_in,
                              void* d_out, int out_size)
{
    const float* x  = (const float*)d_in[0];
    const float* xp = (const float*)d_in[1];
    float* out = (float*)d_out;
    int B = in_sizes[0] / 8;
    int Bo = out_size / 9;
    if (Bo < B) B = Bo;
    dlt_kernel<<<(B + 127) / 128, 128>>>(x, xp, out, B);
}